// round 14
// baseline (speedup 1.0000x reference)
#include <cuda_runtime.h>
#include <cuda_bf16.h>
#include <math.h>
#include <stdint.h>

#define NQ       2048
#define ND       100000
#define DIM      16
#define QTILES   16            // 2048 / 128 queries per CTA
#define DS       37            // data splits; 16*37 = 592 CTAs = 4/SM
#define TILE     256           // data points per smem tile
#define NT       11            // tiles per split
#define PTS_PER_SPLIT (TILE * NT)            // 2816
#define THREADS  256
#define PROW     80            // padded partials row (74 used)
#define ROWW     20            // smem words per point (80 B padded row)

// ---- device scratch (no allocations allowed) ----
__device__ float g_partials[(size_t)NQ * PROW];
__device__ float g_wpart[DS];

// ---- helpers ----
__device__ __forceinline__ uint32_t s2u(const void* p) {
    uint32_t a;
    asm("{ .reg .u64 t; cvta.to.shared.u64 t, %1; cvt.u32.u64 %0, t; }"
        : "=r"(a) : "l"(p));
    return a;
}
// cp.async 16B with src-size (0 -> zero-fill, no global read)
__device__ __forceinline__ void cpa16z(uint32_t dst, const void* src, int sz) {
    asm volatile("cp.async.cg.shared.global [%0], [%1], 16, %2;"
                 :: "r"(dst), "l"(src), "r"(sz));
}
#define CP_COMMIT() asm volatile("cp.async.commit_group;" ::: "memory")
#define CP_WAIT0()  asm volatile("cp.async.wait_group 0;" ::: "memory")
#define CP_WAIT1()  asm volatile("cp.async.wait_group 1;" ::: "memory")

__device__ __forceinline__ float ex2f(float x) {
    float r; asm("ex2.approx.f32 %0, %1;" : "=f"(r) : "f"(x)); return r;
}
__device__ __forceinline__ float tf32r(float x) {
    float r; asm("cvt.rna.tf32.f32 %0, %1;" : "=f"(r) : "f"(x)); return r;
}
__device__ __forceinline__ void mma_tf32(float* d, const uint32_t* a,
                                         uint32_t b0, uint32_t b1) {
    asm volatile(
        "mma.sync.aligned.m16n8k8.row.col.f32.tf32.tf32.f32 "
        "{%0,%1,%2,%3}, {%4,%5,%6,%7}, {%8,%9}, {%0,%1,%2,%3};"
        : "+f"(d[0]), "+f"(d[1]), "+f"(d[2]), "+f"(d[3])
        : "r"(a[0]), "r"(a[1]), "r"(a[2]), "r"(a[3]), "r"(b0), "r"(b1));
}
__device__ __forceinline__ void lds128(uint32_t addr, uint32_t* v) {
    asm volatile("ld.shared.v4.u32 {%0,%1,%2,%3}, [%4];"
                 : "=r"(v[0]), "=r"(v[1]), "=r"(v[2]), "=r"(v[3]) : "r"(addr));
}
__device__ __forceinline__ void sts128(uint32_t addr, const uint32_t* v) {
    asm volatile("st.shared.v4.u32 [%0], {%1,%2,%3,%4};"
                 :: "r"(addr), "r"(v[0]), "r"(v[1]), "r"(v[2]), "r"(v[3]));
}
__device__ __forceinline__ uint32_t lds32(uint32_t addr) {
    uint32_t v;
    asm volatile("ld.shared.u32 %0, [%1];" : "=r"(v) : "r"(addr));
    return v;
}

// ---------------------------------------------------------------------------
// Main (single compute kernel, no prep pass):
//   CTA (qt, ds): 128 queries x 2816 points, tf32 m16n8k8.
//   Per tile: cp.async RAW fp32 points into 80B-padded smem rows (+ raw w),
//   then a short smem phase RNA-rounds to tf32 in place and computes
//   coeff = w * exp(-||d||^2/2), then the MMA/ex2 loop reads B fragments
//   via 4 conflict-free LDS.32 (20-word row stride = perfect bank permute).
// ---------------------------------------------------------------------------
__global__ __launch_bounds__(THREADS, 4)
void kde_main_kernel(const float* __restrict__ X,
                     const float* __restrict__ data,
                     const float* __restrict__ wvec) {
    __shared__ uint32_t sd[2][TILE * ROWW];  // 2 x 20 KB padded raw/rounded
    __shared__ float    sc[2][TILE];         // coeffs
    __shared__ float    sw[2][TILE];         // raw weights
    __shared__ float    redw[THREADS];

    int tid = threadIdx.x;
    int w = tid >> 5, lane = tid & 31;
    int wm = w >> 1, wn = w & 1;
    int qt = blockIdx.x, ds = blockIdx.y;
    int p0base = ds * PTS_PER_SPLIT;
    int r = lane >> 2, cg = lane & 3, c2 = cg * 2;

    const float LOG2E = 1.4426950408889634f;

    // ---- A fragments straight from X ----
    int qb = qt * 128 + wm * 32;
    uint32_t afrag[2][2][4];
#pragma unroll
    for (int mt = 0; mt < 2; mt++)
#pragma unroll
        for (int kc = 0; kc < 2; kc++) {
            int q0 = qb + mt * 16 + r;
            int k0 = kc * 8 + cg;
            afrag[mt][kc][0] = __float_as_uint(tf32r(X[(size_t)q0 * 16 + k0] * LOG2E));
            afrag[mt][kc][1] = __float_as_uint(tf32r(X[(size_t)(q0 + 8) * 16 + k0] * LOG2E));
            afrag[mt][kc][2] = __float_as_uint(tf32r(X[(size_t)q0 * 16 + k0 + 4] * LOG2E));
            afrag[mt][kc][3] = __float_as_uint(tf32r(X[(size_t)(q0 + 8) * 16 + k0 + 4] * LOG2E));
        }

    // ---- staging macro: raw data + w for tile IT into buffer BUF ----
#define STAGE(BUF, IT)                                                       \
    {                                                                        \
        int p0_ = p0base + (IT) * TILE;                                      \
        uint32_t sbb_ = s2u(sd[BUF]);                                        \
        _Pragma("unroll")                                                    \
        for (int i = tid; i < TILE * 4; i += THREADS) {                      \
            int row_ = i >> 2, c_ = i & 3;                                   \
            int j_ = p0_ + row_;                                             \
            const char* src_ = (const char*)data + (size_t)j_ * 64 + c_ * 16;\
            cpa16z(sbb_ + row_ * 80 + c_ * 16, src_, (j_ < ND) ? 16 : 0);    \
        }                                                                    \
        if (tid < 64) {                                                      \
            int j4_ = p0_ + tid * 4;                                         \
            cpa16z(s2u(sw[BUF]) + tid * 16,                                  \
                   (const char*)wvec + (size_t)j4_ * 4, (j4_ < ND) ? 16 : 0);\
        }                                                                    \
        CP_COMMIT();                                                         \
    }

    STAGE(0, 0);

    float acc[2][2] = {{0.0f, 0.0f}, {0.0f, 0.0f}};
    float wacc = 0.0f;
    int buf = 0;

    for (int it = 0; it < NT; ++it) {
        if (it + 1 < NT) {
            STAGE(buf ^ 1, it + 1);
            CP_WAIT1();   // tile `it` resident
        } else {
            CP_WAIT0();
        }
        __syncthreads();

        // ---- round + coeff phase: thread tid owns point tid of this tile --
        {
            uint32_t rowa = s2u(sd[buf]) + (uint32_t)tid * 80;
            uint32_t v[16];
            lds128(rowa, v);
            lds128(rowa + 16, v + 4);
            lds128(rowa + 32, v + 8);
            lds128(rowa + 48, v + 12);
            float dn = 0.0f;
#pragma unroll
            for (int k = 0; k < 16; k++) {
                float f = tf32r(__uint_as_float(v[k]));
                v[k] = __float_as_uint(f);
                dn = fmaf(f, f, dn);
            }
            sts128(rowa, v);
            sts128(rowa + 16, v + 4);
            sts128(rowa + 32, v + 8);
            sts128(rowa + 48, v + 12);
            float wj = sw[buf][tid];
            sc[buf][tid] = wj * ex2f(-0.72134752044448170f * dn);
            wacc += wj;
        }
        __syncthreads();

        uint32_t sdb = s2u(sd[buf]);
        const float* scf = sc[buf];
#pragma unroll
        for (int nt = 0; nt < 16; nt++) {
            int n0 = wn * 128 + nt * 8;
            uint32_t base = sdb + (uint32_t)(n0 + r) * 80 + (uint32_t)cg * 4;
            uint32_t b0 = lds32(base);        // word cg      (kc0 lo)
            uint32_t b1 = lds32(base + 16);   // word cg + 4  (kc0 hi)
            uint32_t b2 = lds32(base + 32);   // word cg + 8  (kc1 lo)
            uint32_t b3 = lds32(base + 48);   // word cg + 12 (kc1 hi)
            float d0[4] = {0, 0, 0, 0}, d1[4] = {0, 0, 0, 0};
            mma_tf32(d0, afrag[0][0], b0, b1);
            mma_tf32(d1, afrag[1][0], b0, b1);
            mma_tf32(d0, afrag[0][1], b2, b3);
            mma_tf32(d1, afrag[1][1], b2, b3);

            float2 cj = *(const float2*)(scf + n0 + c2);
            acc[0][0] = fmaf(cj.x, ex2f(d0[0]), acc[0][0]);
            acc[0][0] = fmaf(cj.y, ex2f(d0[1]), acc[0][0]);
            acc[0][1] = fmaf(cj.x, ex2f(d0[2]), acc[0][1]);
            acc[0][1] = fmaf(cj.y, ex2f(d0[3]), acc[0][1]);
            acc[1][0] = fmaf(cj.x, ex2f(d1[0]), acc[1][0]);
            acc[1][0] = fmaf(cj.y, ex2f(d1[1]), acc[1][0]);
            acc[1][1] = fmaf(cj.x, ex2f(d1[2]), acc[1][1]);
            acc[1][1] = fmaf(cj.y, ex2f(d1[3]), acc[1][1]);
        }
        __syncthreads();  // done reading buf before restage next iter
        buf ^= 1;
    }
#undef STAGE

    // per-split w sum (identical in all 16 qt CTAs; qt==0 publishes)
    if (qt == 0) {
        redw[tid] = wacc;
        __syncthreads();
#pragma unroll
        for (int s = THREADS / 2; s > 0; s >>= 1) {
            if (tid < s) redw[tid] += redw[tid + s];
            __syncthreads();
        }
        if (tid == 0) g_wpart[ds] = redw[0];
    }

    // Reduce over the 4 column-lanes (fixed order, deterministic)
#pragma unroll
    for (int mt = 0; mt < 2; mt++)
#pragma unroll
        for (int hh = 0; hh < 2; hh++) {
            float v = acc[mt][hh];
            v += __shfl_xor_sync(0xFFFFFFFFu, v, 1);
            v += __shfl_xor_sync(0xFFFFFFFFu, v, 2);
            acc[mt][hh] = v;
        }
    if (cg == 0) {
        int col = ds * 2 + wn;
        g_partials[(size_t)(qb + r) * PROW + col]          = acc[0][0];
        g_partials[(size_t)(qb + r + 8) * PROW + col]      = acc[0][1];
        g_partials[(size_t)(qb + 16 + r) * PROW + col]     = acc[1][0];
        g_partials[(size_t)(qb + 16 + r + 8) * PROW + col] = acc[1][1];
    }
}

// ---------------------------------------------------------------------------
// Finalize: warp per query (PDL: ||x||^2 before grid sync). logsumw from the
// 37 per-split sums (fixed order, deterministic).
//   log_density = log(S) - 0.5||x||^2 - 8*log(2*pi) - logsumw
// ---------------------------------------------------------------------------
__global__ __launch_bounds__(256)
void kde_final_kernel(const float* __restrict__ X,
                      float* __restrict__ out) {
    __shared__ float s_logsumw;
    int t = threadIdx.x;
    int w = t >> 5, lane = t & 31;
    int q = blockIdx.x * 8 + w;

    // prep-independent prolog
    float qn = 0.0f;
    {
        const float4* row = (const float4*)(X + (size_t)q * DIM);
#pragma unroll
        for (int v = 0; v < 4; v++) {
            float4 p = row[v];
            qn += p.x * p.x + p.y * p.y + p.z * p.z + p.w * p.w;
        }
    }

    cudaGridDependencySynchronize();

    if (w == 0) {
        float s = g_wpart[lane & 31];          // lanes 0..31 -> slots 0..31
        if (lane >= 32 - (DS - 32)) {}         // (no-op, clarity)
        if (lane < DS - 32) s += g_wpart[lane + 32];
        s += __shfl_xor_sync(0xFFFFFFFFu, s, 16);
        s += __shfl_xor_sync(0xFFFFFFFFu, s, 8);
        s += __shfl_xor_sync(0xFFFFFFFFu, s, 4);
        s += __shfl_xor_sync(0xFFFFFFFFu, s, 2);
        s += __shfl_xor_sync(0xFFFFFFFFu, s, 1);
        if (lane == 0) s_logsumw = logf(s);
    }
    __syncthreads();

    const float* pr = g_partials + (size_t)q * PROW;
    float S = pr[lane] + pr[lane + 32];
    if (lane < DS * 2 - 64) S += pr[lane + 64];
    // fixed-order shfl reduction
    S += __shfl_xor_sync(0xFFFFFFFFu, S, 16);
    S += __shfl_xor_sync(0xFFFFFFFFu, S, 8);
    S += __shfl_xor_sync(0xFFFFFFFFu, S, 4);
    S += __shfl_xor_sync(0xFFFFFFFFu, S, 2);
    S += __shfl_xor_sync(0xFFFFFFFFu, S, 1);

    if (lane == 0) {
        const float LOG2PI = 1.8378770664093453f;
        out[q] = logf(S) - 0.5f * qn - 8.0f * LOG2PI - s_logsumw;
    }
}

// ---------------------------------------------------------------------------
extern "C" void kernel_launch(void* const* d_in, const int* in_sizes, int n_in,
                              void* d_out, int out_size) {
    const float* X    = (const float*)d_in[0];  // [2048, 16]
    const float* data = (const float*)d_in[1];  // [100000, 16]
    const float* w    = (const float*)d_in[2];  // [100000]
    float* out = (float*)d_out;                 // [2048]

    kde_main_kernel<<<dim3(QTILES, DS), THREADS>>>(X, data, w);

    cudaLaunchAttribute attr[1];
    attr[0].id = cudaLaunchAttributeProgrammaticStreamSerialization;
    attr[0].val.programmaticStreamSerializationAllowed = 1;

    cudaLaunchConfig_t cfg = {};
    cfg.gridDim = dim3(NQ / 8);
    cfg.blockDim = dim3(256);
    cfg.dynamicSmemBytes = 0;
    cfg.attrs = attr;
    cfg.numAttrs = 1;
    cudaLaunchKernelEx(&cfg, kde_final_kernel, X, out);
}

// round 15
// speedup vs baseline: 1.1411x; 1.1411x over previous
#include <cuda_runtime.h>
#include <cuda_bf16.h>
#include <math.h>
#include <stdint.h>

#define NQ       2048
#define ND       100000
#define DIM      16
#define QTILES   16            // 2048 / 128 queries per CTA
#define DS       37            // data splits; 16*37 = 592 CTAs = 4/SM
#define TILE     256           // data points per smem tile
#define NT       11            // tiles per split
#define PTS_PER_SPLIT (TILE * NT)            // 2816
#define NPAD     (DS * PTS_PER_SPLIT)        // 104192
#define THREADS  256
#define PREP_BLOCKS  204       // 204 * 512 = 104448 >= NPAD (2 points/thread)
#define PREP_THREADS 256
#define PROW     80            // padded partials row (74 used)

// ---- device scratch (no allocations allowed) ----
// g_dcat: per point, 16 tf32 words, PERMUTED: pos 4g+{0..3} = natural words
//         {g, g+4, g+8, g+12}. One LDS.128 per lane yields both k8 B
//         fragments (b0_kc0, b1_kc0, b0_kc1, b1_kc1) for m16n8k8 tf32.
__device__ float4 g_dcat[(size_t)NPAD * 4];
__device__ float g_coeff[NPAD];             // w_j * exp(-0.5*||d||^2)
__device__ float g_partials[(size_t)NQ * PROW];
__device__ float g_wpart[PREP_BLOCKS];
__device__ float g_logsumw;

// ---- helpers ----
__device__ __forceinline__ uint32_t s2u(const void* p) {
    uint32_t a;
    asm("{ .reg .u64 t; cvta.to.shared.u64 t, %1; cvt.u32.u64 %0, t; }"
        : "=r"(a) : "l"(p));
    return a;
}
__device__ __forceinline__ void cpa16(uint32_t dst, const void* src) {
    asm volatile("cp.async.cg.shared.global [%0], [%1], 16;"
                 :: "r"(dst), "l"(src));
}
#define CP_COMMIT() asm volatile("cp.async.commit_group;" ::: "memory")
#define CP_WAIT0()  asm volatile("cp.async.wait_group 0;" ::: "memory")
#define CP_WAIT1()  asm volatile("cp.async.wait_group 1;" ::: "memory")

__device__ __forceinline__ float ex2f(float x) {
    float r; asm("ex2.approx.f32 %0, %1;" : "=f"(r) : "f"(x)); return r;
}
__device__ __forceinline__ float tf32r(float x) {
    float r; asm("cvt.rna.tf32.f32 %0, %1;" : "=f"(r) : "f"(x)); return r;
}
__device__ __forceinline__ void mma_tf32(float* d, const uint32_t* a,
                                         uint32_t b0, uint32_t b1) {
    asm volatile(
        "mma.sync.aligned.m16n8k8.row.col.f32.tf32.tf32.f32 "
        "{%0,%1,%2,%3}, {%4,%5,%6,%7}, {%8,%9}, {%0,%1,%2,%3};"
        : "+f"(d[0]), "+f"(d[1]), "+f"(d[2]), "+f"(d[3])
        : "r"(a[0]), "r"(a[1]), "r"(a[2]), "r"(a[3]), "r"(b0), "r"(b1));
}
__device__ __forceinline__ void lds128(uint32_t addr, uint32_t* v) {
    asm volatile("ld.shared.v4.u32 {%0,%1,%2,%3}, [%4];"
                 : "=r"(v[0]), "=r"(v[1]), "=r"(v[2]), "=r"(v[3]) : "r"(addr));
}

// ---------------------------------------------------------------------------
// Prep: TWO points per thread (deep MLP — all 8 LDG.128 + 2 LDG.32 issued
// before any compute). tf32 permuted layout + coeff. Warp-shfl w reduction
// (1 sync instead of 8).
// ---------------------------------------------------------------------------
__global__ __launch_bounds__(PREP_THREADS)
void kde_prep_kernel(const float* __restrict__ data,
                     const float* __restrict__ w) {
    int t = threadIdx.x;
    int base = blockIdx.x * 512;
    int j0 = base + t, j1 = base + t + 256;
    bool v0 = j0 < ND, v1 = j1 < ND;

    const float4 Z4 = make_float4(0.f, 0.f, 0.f, 0.f);
    float4 p0[4], p1[4];
    const float4* s0 = (const float4*)(data + (size_t)j0 * DIM);
    const float4* s1 = (const float4*)(data + (size_t)j1 * DIM);
#pragma unroll
    for (int v = 0; v < 4; v++) p0[v] = v0 ? s0[v] : Z4;
#pragma unroll
    for (int v = 0; v < 4; v++) p1[v] = v1 ? s1[v] : Z4;
    float w0 = v0 ? w[j0] : 0.0f;
    float w1 = v1 ? w[j1] : 0.0f;

    // process point 0
    if (j0 < NPAD) {
        float e[16], dn = 0.0f;
#pragma unroll
        for (int v = 0; v < 4; v++) {
            e[v*4+0] = p0[v].x; e[v*4+1] = p0[v].y;
            e[v*4+2] = p0[v].z; e[v*4+3] = p0[v].w;
        }
#pragma unroll
        for (int k = 0; k < 16; k++) { dn = fmaf(e[k], e[k], dn); e[k] = tf32r(e[k]); }
        g_coeff[j0] = w0 * ex2f(-0.72134752044448170f * dn);
#pragma unroll
        for (int g = 0; g < 4; g++) {
            float4 o;
            o.x = e[g]; o.y = e[g+4]; o.z = e[g+8]; o.w = e[g+12];
            g_dcat[(size_t)j0 * 4 + g] = o;
        }
    }
    // process point 1
    if (j1 < NPAD) {
        float e[16], dn = 0.0f;
#pragma unroll
        for (int v = 0; v < 4; v++) {
            e[v*4+0] = p1[v].x; e[v*4+1] = p1[v].y;
            e[v*4+2] = p1[v].z; e[v*4+3] = p1[v].w;
        }
#pragma unroll
        for (int k = 0; k < 16; k++) { dn = fmaf(e[k], e[k], dn); e[k] = tf32r(e[k]); }
        g_coeff[j1] = w1 * ex2f(-0.72134752044448170f * dn);
#pragma unroll
        for (int g = 0; g < 4; g++) {
            float4 o;
            o.x = e[g]; o.y = e[g+4]; o.z = e[g+8]; o.w = e[g+12];
            g_dcat[(size_t)j1 * 4 + g] = o;
        }
    }

    // w reduction: warp shfl, then warp 0 sums the 8 per-warp values
    __shared__ float redw[8];
    float s = w0 + w1;
    s += __shfl_xor_sync(0xFFFFFFFFu, s, 16);
    s += __shfl_xor_sync(0xFFFFFFFFu, s, 8);
    s += __shfl_xor_sync(0xFFFFFFFFu, s, 4);
    s += __shfl_xor_sync(0xFFFFFFFFu, s, 2);
    s += __shfl_xor_sync(0xFFFFFFFFu, s, 1);
    if ((t & 31) == 0) redw[t >> 5] = s;
    __syncthreads();
    if (t == 0) {
        float r = 0.0f;
#pragma unroll
        for (int i = 0; i < 8; i++) r += redw[i];
        g_wpart[blockIdx.x] = r;
    }
}

// ---------------------------------------------------------------------------
// Main: CTA (qt, ds): 128 queries x 2816 points, tf32 m16n8k8 (R7 loop).
// PDL: A fragments computed from raw X (prep-independent) BEFORE
// cudaGridDependencySynchronize(); staging/g_wpart reads come after.
// CTA (0,0) reduces g_wpart -> g_logsumw (hidden under the wave).
// ---------------------------------------------------------------------------
__global__ __launch_bounds__(THREADS, 4)
void kde_main_kernel(const float* __restrict__ X) {
    __shared__ uint4 sd[2][TILE * 4];   // 2 x 16 KB, 64B per point (permuted)
    __shared__ float sc[2][TILE];

    int tid = threadIdx.x;
    int w = tid >> 5, lane = tid & 31;
    int wm = w >> 1, wn = w & 1;
    int qt = blockIdx.x, ds = blockIdx.y;
    int p0base = ds * PTS_PER_SPLIT;
    int r = lane >> 2, cg = lane & 3, c2 = cg * 2;

    const float LOG2E = 1.4426950408889634f;

    // ---- prep-independent prolog: A fragments straight from X ----
    int qb = qt * 128 + wm * 32;
    uint32_t afrag[2][2][4];
#pragma unroll
    for (int mt = 0; mt < 2; mt++)
#pragma unroll
        for (int kc = 0; kc < 2; kc++) {
            int q0 = qb + mt * 16 + r;
            int k0 = kc * 8 + cg;
            afrag[mt][kc][0] = __float_as_uint(tf32r(X[(size_t)q0 * 16 + k0] * LOG2E));
            afrag[mt][kc][1] = __float_as_uint(tf32r(X[(size_t)(q0 + 8) * 16 + k0] * LOG2E));
            afrag[mt][kc][2] = __float_as_uint(tf32r(X[(size_t)q0 * 16 + k0 + 4] * LOG2E));
            afrag[mt][kc][3] = __float_as_uint(tf32r(X[(size_t)(q0 + 8) * 16 + k0 + 4] * LOG2E));
        }

    // ---- wait for prep kernel's writes to be visible ----
    cudaGridDependencySynchronize();

    // CTA (0,0), warp 0: logsumw (fixed order per lane -> deterministic)
    if (qt == 0 && ds == 0 && w == 0) {
        float s = 0.0f;
        for (int b = lane; b < PREP_BLOCKS; b += 32) s += g_wpart[b];
        s += __shfl_xor_sync(0xFFFFFFFFu, s, 16);
        s += __shfl_xor_sync(0xFFFFFFFFu, s, 8);
        s += __shfl_xor_sync(0xFFFFFFFFu, s, 4);
        s += __shfl_xor_sync(0xFFFFFFFFu, s, 2);
        s += __shfl_xor_sync(0xFFFFFFFFu, s, 1);
        if (lane == 0) g_logsumw = logf(s);
    }

    // Stage tile 0
    {
        const char* bsrc = (const char*)(g_dcat + (size_t)p0base * 4);
        uint32_t sbb = s2u(sd[0]);
#pragma unroll
        for (int i = tid; i < TILE * 4; i += THREADS)
            cpa16(sbb + i * 16, bsrc + i * 16);
        if (tid < 64)
            cpa16(s2u(sc[0]) + tid * 16, (const char*)(g_coeff + p0base) + tid * 16);
        CP_COMMIT();
    }

    float acc[2][2] = {{0.0f, 0.0f}, {0.0f, 0.0f}};
    int buf = 0;

    for (int it = 0; it < NT; ++it) {
        if (it + 1 < NT) {
            int p0 = p0base + (it + 1) * TILE;
            const char* bsrc = (const char*)(g_dcat + (size_t)p0 * 4);
            uint32_t sbb = s2u(sd[buf ^ 1]);
#pragma unroll
            for (int i = tid; i < TILE * 4; i += THREADS)
                cpa16(sbb + i * 16, bsrc + i * 16);
            if (tid < 64)
                cpa16(s2u(sc[buf ^ 1]) + tid * 16, (const char*)(g_coeff + p0) + tid * 16);
            CP_COMMIT();
            CP_WAIT1();   // tile `it` resident
        } else {
            CP_WAIT0();
        }
        __syncthreads();

        uint32_t sdb = s2u(sd[buf]);
        const float* scf = sc[buf];
#pragma unroll
        for (int nt = 0; nt < 16; nt++) {
            int n0 = wn * 128 + nt * 8;
            uint32_t b[4];
            lds128(sdb + (uint32_t)(n0 + r) * 64 + (uint32_t)cg * 16, b);
            float d0[4] = {0, 0, 0, 0}, d1[4] = {0, 0, 0, 0};
            // b[0],b[1] = k-chunk 0 fragment; b[2],b[3] = k-chunk 1
            mma_tf32(d0, afrag[0][0], b[0], b[1]);
            mma_tf32(d1, afrag[1][0], b[0], b[1]);
            mma_tf32(d0, afrag[0][1], b[2], b[3]);
            mma_tf32(d1, afrag[1][1], b[2], b[3]);

            float2 cj = *(const float2*)(scf + n0 + c2);
            acc[0][0] = fmaf(cj.x, ex2f(d0[0]), acc[0][0]);
            acc[0][0] = fmaf(cj.y, ex2f(d0[1]), acc[0][0]);
            acc[0][1] = fmaf(cj.x, ex2f(d0[2]), acc[0][1]);
            acc[0][1] = fmaf(cj.y, ex2f(d0[3]), acc[0][1]);
            acc[1][0] = fmaf(cj.x, ex2f(d1[0]), acc[1][0]);
            acc[1][0] = fmaf(cj.y, ex2f(d1[1]), acc[1][0]);
            acc[1][1] = fmaf(cj.x, ex2f(d1[2]), acc[1][1]);
            acc[1][1] = fmaf(cj.y, ex2f(d1[3]), acc[1][1]);
        }
        __syncthreads();  // done reading buf before restage
        buf ^= 1;
    }

    // Reduce over the 4 column-lanes (fixed order, deterministic)
#pragma unroll
    for (int mt = 0; mt < 2; mt++)
#pragma unroll
        for (int hh = 0; hh < 2; hh++) {
            float v = acc[mt][hh];
            v += __shfl_xor_sync(0xFFFFFFFFu, v, 1);
            v += __shfl_xor_sync(0xFFFFFFFFu, v, 2);
            acc[mt][hh] = v;
        }
    if (cg == 0) {
        int col = ds * 2 + wn;
        g_partials[(size_t)(qb + r) * PROW + col]          = acc[0][0];
        g_partials[(size_t)(qb + r + 8) * PROW + col]      = acc[0][1];
        g_partials[(size_t)(qb + 16 + r) * PROW + col]     = acc[1][0];
        g_partials[(size_t)(qb + 16 + r + 8) * PROW + col] = acc[1][1];
    }
}

// ---------------------------------------------------------------------------
// Finalize: warp per query. PDL: ||x||^2 (input-only) computed BEFORE
// cudaGridDependencySynchronize(); partials + logsumw read after.
//   log_density = log(S) - 0.5||x||^2 - 8*log(2*pi) - logsumw
// ---------------------------------------------------------------------------
__global__ __launch_bounds__(256)
void kde_final_kernel(const float* __restrict__ X,
                      float* __restrict__ out) {
    int t = threadIdx.x;
    int w = t >> 5, lane = t & 31;
    int q = blockIdx.x * 8 + w;

    // prep-independent prolog
    float qn = 0.0f;
    {
        const float4* row = (const float4*)(X + (size_t)q * DIM);
#pragma unroll
        for (int v = 0; v < 4; v++) {
            float4 p = row[v];
            qn += p.x * p.x + p.y * p.y + p.z * p.z + p.w * p.w;
        }
    }

    cudaGridDependencySynchronize();

    const float* pr = g_partials + (size_t)q * PROW;
    float S = pr[lane] + pr[lane + 32];
    if (lane < DS * 2 - 64) S += pr[lane + 64];
    // fixed-order shfl reduction
    S += __shfl_xor_sync(0xFFFFFFFFu, S, 16);
    S += __shfl_xor_sync(0xFFFFFFFFu, S, 8);
    S += __shfl_xor_sync(0xFFFFFFFFu, S, 4);
    S += __shfl_xor_sync(0xFFFFFFFFu, S, 2);
    S += __shfl_xor_sync(0xFFFFFFFFu, S, 1);

    if (lane == 0) {
        const float LOG2PI = 1.8378770664093453f;
        out[q] = logf(S) - 0.5f * qn - 8.0f * LOG2PI - g_logsumw;
    }
}

// ---------------------------------------------------------------------------
extern "C" void kernel_launch(void* const* d_in, const int* in_sizes, int n_in,
                              void* d_out, int out_size) {
    const float* X    = (const float*)d_in[0];  // [2048, 16]
    const float* data = (const float*)d_in[1];  // [100000, 16]
    const float* w    = (const float*)d_in[2];  // [100000]
    float* out = (float*)d_out;                 // [2048]

    kde_prep_kernel<<<PREP_BLOCKS, PREP_THREADS>>>(data, w);

    cudaLaunchAttribute attr[1];
    attr[0].id = cudaLaunchAttributeProgrammaticStreamSerialization;
    attr[0].val.programmaticStreamSerializationAllowed = 1;

    {
        cudaLaunchConfig_t cfg = {};
        cfg.gridDim = dim3(QTILES, DS);
        cfg.blockDim = dim3(THREADS);
        cfg.dynamicSmemBytes = 0;
        cfg.attrs = attr;
        cfg.numAttrs = 1;
        cudaLaunchKernelEx(&cfg, kde_main_kernel, X);
    }
    {
        cudaLaunchConfig_t cfg = {};
        cfg.gridDim = dim3(NQ / 8);
        cfg.blockDim = dim3(256);
        cfg.dynamicSmemBytes = 0;
        cfg.attrs = attr;
        cfg.numAttrs = 1;
        cudaLaunchKernelEx(&cfg, kde_final_kernel, X, out);
    }
}